// round 17
// baseline (speedup 1.0000x reference)
#include <cuda_runtime.h>
#include <cuda_bf16.h>

#define Dm 1024
#define Tm 2048
#define Lm 4

typedef unsigned long long u64;

// ---------------- device scratch (allocation-free rule) ---------------------
__device__ __align__(16)  float g_seq[2][Tm * Dm];              // ping-pong seq
__device__ __align__(16)  float g_zx[(size_t)Tm * 4 * Dm];      // x-part + bias
__device__ __align__(16)  float g_wt[(size_t)Lm * 4 * Dm * Dm]; // Wh^T [l][gate][dim][k]
__device__ __align__(128) u64   g_ht[2][Dm];                    // {tag<<32 | h bits}
__device__ unsigned g_bar_count;                                // monotonic / launch

// ---------------- f32x2 helpers (sm_103a packed fp32) -----------------------
__device__ __forceinline__ u64 ffma2(u64 a, u64 b, u64 c) {
    u64 d;
    asm("fma.rn.f32x2 %0, %1, %2, %3;" : "=l"(d) : "l"(a), "l"(b), "l"(c));
    return d;
}
__device__ __forceinline__ u64 fadd2(u64 a, u64 b) {
    u64 d;
    asm("add.rn.f32x2 %0, %1, %2;" : "=l"(d) : "l"(a), "l"(b));
    return d;
}
__device__ __forceinline__ u64 pack2(float x, float y) {
    u64 r;
    asm("mov.b64 %0, {%1, %2};" : "=l"(r)
        : "r"(__float_as_uint(x)), "r"(__float_as_uint(y)));
    return r;
}
__device__ __forceinline__ float hsum2(u64 v) {
    unsigned lo, hi;
    asm("mov.b64 {%0, %1}, %2;" : "=r"(lo), "=r"(hi) : "l"(v));
    return __uint_as_float(lo) + __uint_as_float(hi);
}

// fast, saturation-safe tanh / sigmoid (MUFU-based)
__device__ __forceinline__ float fast_tanh(float x) {
    float e = __expf(-2.0f * fabsf(x));
    float r = __fdividef(1.0f - e, 1.0f + e);
    return copysignf(r, x);
}
__device__ __forceinline__ float fast_sigmoid(float u) {
    float e = __expf(-fabsf(u));
    float r = __fdividef(1.0f, 1.0f + e);
    return (u >= 0.0f) ? r : (1.0f - r);
}

// ---------------- kernel 1: Re bias-add + barrier/tag reset ------------------
__global__ void bias_kernel(const float* __restrict__ x, const float* __restrict__ rn,
                            const float* __restrict__ w, const float* __restrict__ b) {
    if (blockIdx.x == 0 && threadIdx.x == 0) g_bar_count = 0u;
    int i = blockIdx.x * 256 + threadIdx.x;
    if (i < Dm) { g_ht[0][i] = 0ull; g_ht[1][i] = 0ull; }   // kill stale tags
    int j = i & (Dm - 1);
    g_seq[0][i] = x[i] + rn[0] * w[j] + b[j];
}

// ---------------- kernel 1b: transpose Wh -> g_wt[l][gate][dim][k] ----------
__global__ void wt_kernel(const float* __restrict__ Wf1, const float* __restrict__ Wf2,
                          const float* __restrict__ Wta, const float* __restrict__ Wtb) {
    __shared__ float tile[32][33];
    const int lg = blockIdx.z;              // l*4 + gate
    const int l = lg >> 2, gate = lg & 3;
    const float* Wg = (gate == 0) ? Wf1 : ((gate == 1) ? Wf2 : ((gate == 2) ? Wta : Wtb));
    const float* W = Wg + (size_t)l * 2 * Dm * Dm;
    const int k0 = blockIdx.x * 32, d0 = blockIdx.y * 32;
    const int tx = threadIdx.x, ty = threadIdx.y;
#pragma unroll
    for (int r = ty; r < 32; r += 8)
        tile[r][tx] = W[(size_t)(Dm + k0 + r) * Dm + d0 + tx];   // h-part rows
    __syncthreads();
#pragma unroll
    for (int r = ty; r < 32; r += 8)
        g_wt[((size_t)lg * Dm + d0 + r) * Dm + k0 + tx] = tile[tx][r];
}

// ---------------- kernel 2: Zx = seq_in @ Wx + bias (f32x2 GEMM) -------------
// C tile 128(m) x 128(n), BK=16, 256 threads, 8x8 packed accs per thread.
__global__ __launch_bounds__(256, 1) void gemm_zx(
    const float* __restrict__ Wf1, const float* __restrict__ Wf2,
    const float* __restrict__ Wta, const float* __restrict__ Wtb,
    const float* __restrict__ bf1, const float* __restrict__ bf2,
    const float* __restrict__ bta, const float* __restrict__ btb,
    int layer)
{
    __shared__ u64   As2[8][128];       // [k-pair][m]  8KB
    __shared__ float Bsf[8][128][2];    // [k-pair][n][k parity]  8KB

    const int tid = threadIdx.x;
    const int tx = tid & 15;
    const int ty = tid >> 4;
    const int m0 = blockIdx.y * 128;
    const int n0 = blockIdx.x * 128;    // 0..4096 step 128, within one gate
    const int blk = n0 >> 10;
    const int j0  = n0 & (Dm - 1);

    const float* Wb = (blk == 0) ? Wf1 : ((blk == 1) ? Wf2 : ((blk == 2) ? Wta : Wtb));
    const float* bb = (blk == 0) ? bf1 : ((blk == 1) ? bf2 : ((blk == 2) ? bta : btb));
    const float* Bp = Wb + (size_t)layer * 2 * Dm * Dm + j0;
    const float* A  = g_seq[layer & 1];

    u64 acc[8][8];
#pragma unroll
    for (int i = 0; i < 8; i++)
#pragma unroll
        for (int j = 0; j < 8; j++) acc[i][j] = 0ull;

    for (int k0 = 0; k0 < Dm; k0 += 16) {
#pragma unroll
        for (int it = 0; it < 2; it++) {       // A: 512 float4, 2/thread
            int i   = tid + it * 256;
            int row = i >> 2;
            int f4  = i & 3;
            float4 v = *(const float4*)(A + (size_t)(m0 + row) * Dm + k0 + f4 * 4);
            As2[f4 * 2 + 0][row] = pack2(v.x, v.y);
            As2[f4 * 2 + 1][row] = pack2(v.z, v.w);
        }
#pragma unroll
        for (int it = 0; it < 2; it++) {       // B: 512 float4, 2/thread
            int i   = tid + it * 256;
            int kr  = i >> 5;                  // 0..15
            int j4  = i & 31;                  // 0..31
            float4 v = *(const float4*)(Bp + (size_t)(k0 + kr) * Dm + j4 * 4);
            Bsf[kr >> 1][j4 * 4 + 0][kr & 1] = v.x;
            Bsf[kr >> 1][j4 * 4 + 1][kr & 1] = v.y;
            Bsf[kr >> 1][j4 * 4 + 2][kr & 1] = v.z;
            Bsf[kr >> 1][j4 * 4 + 3][kr & 1] = v.w;
        }
        __syncthreads();
#pragma unroll
        for (int kk = 0; kk < 8; kk++) {
            u64 a2[8], b2[8];
#pragma unroll
            for (int ii = 0; ii < 8; ii++) a2[ii] = As2[kk][ii * 16 + ty];
#pragma unroll
            for (int jj = 0; jj < 8; jj++) b2[jj] = *(const u64*)&Bsf[kk][jj * 16 + tx][0];
#pragma unroll
            for (int ii = 0; ii < 8; ii++)
#pragma unroll
                for (int jj = 0; jj < 8; jj++)
                    acc[ii][jj] = ffma2(a2[ii], b2[jj], acc[ii][jj]);
        }
        __syncthreads();
    }

    float bias[8];
#pragma unroll
    for (int jj = 0; jj < 8; jj++) bias[jj] = bb[(size_t)layer * Dm + j0 + jj * 16 + tx];
#pragma unroll
    for (int ii = 0; ii < 8; ii++) {
        size_t row = (size_t)(m0 + ii * 16 + ty);
#pragma unroll
        for (int jj = 0; jj < 8; jj++)
            g_zx[row * 4096 + n0 + jj * 16 + tx] = hsum2(acc[ii][jj]) + bias[jj];
    }
}

// ---------------- kernel 3: sequential scan ----------------------------------
// 128 CTAs x 256 threads. CTA b owns dims 8b..8b+7, warp w -> dim.
// Lane = blk*8 + chunk. Counter barrier (warp0, 2-deep pipelined poll);
// publish = ONE tagged 8B st.relaxed; arrival = smem warp-count -> 8th warp
// fires red.relaxed (no fence; tags self-verify staging). 2 BARs/step.
__global__ __launch_bounds__(256, 1) void scan_kernel(const float* __restrict__ dt_ptr,
                                                      int layer)
{
    __shared__ __align__(16) float sh[2][Dm];   // double-buffered h stage
    __shared__ unsigned s_acnt;                  // warp arrivals (monotonic)

    const int tid  = threadIdx.x;
    const int lane = tid & 31;
    const int w    = tid >> 5;
    const int blk  = lane >> 3;
    const int ch   = lane & 7;
    const int dim  = blockIdx.x * 8 + w;
    const float dt = dt_ptr[0];
    const unsigned tagb = (unsigned)layer * (unsigned)Tm;
    const unsigned cntb = (unsigned)layer * 2047u * 128u;
    unsigned* const cnt = &g_bar_count;
    const unsigned acnt_a = (unsigned)__cvta_generic_to_shared(&s_acnt);
    if (tid == 0) s_acnt = 0u;

    // coalesced weight load from transposed scratch: [l][gate][dim][k]
    const float* Wtp = g_wt + ((size_t)(layer * 4 + blk) * Dm + dim) * Dm + ch * 128;
    u64 wreg[64];
#pragma unroll
    for (int i = 0; i < 32; i++) {
        float4 v = *(const float4*)(Wtp + 4 * i);
        wreg[2 * i + 0] = pack2(v.x, v.y);
        wreg[2 * i + 1] = pack2(v.z, v.w);
    }

    float* __restrict__ outseq = g_seq[(layer + 1) & 1];
    const bool zlane = (ch == 0);
    float zx_cur = zlane ? __ldg(&g_zx[(size_t)blk * Dm + dim]) : 0.0f;
    float h_keep = 0.0f;   // outseq stash: step (t & ~15) + lane, lanes 0-15

    // staging indices: thread handles h[sc*128 + sf*4 .. +3]
    const int sc = tid & 7, sf = tid >> 3;
    const int htoff = sc * 128 + sf * 4;
    float* const mysh0 = &sh[0][sf * 32 + sc * 4];
    float* const mysh1 = &sh[1][sf * 32 + sc * 4];

    for (int t = 0; t < Tm; ++t) {
        // ---- detect: warp0 2-deep pipelined poll of ONE counter word ----
        if (t > 0) {
            if (w == 0) {
                const unsigned target = cntb + 128u * (unsigned)t;
                unsigned v0, v1;
                for (;;) {
                    asm volatile("ld.relaxed.gpu.global.u32 %0, [%1];"
                                 : "=r"(v0) : "l"(cnt) : "memory");
                    asm volatile("ld.relaxed.gpu.global.u32 %0, [%1];"
                                 : "=r"(v1) : "l"(cnt) : "memory");
                    if ((int)(v0 - target) >= 0 || (int)(v1 - target) >= 0) break;
                }
            }
            __syncthreads();   // BAR A: detect done (also covers s_acnt init)
        }

        // ---- stage h_t (tag-verified) ----
        float* mysh = (t & 1) ? mysh1 : mysh0;
        if (t == 0) {
            mysh[0] = 0.0f; mysh[1] = 0.0f; mysh[2] = 0.0f; mysh[3] = 0.0f;
        } else {
            const u64* pp = &g_ht[t & 1][htoff];
            const unsigned target = tagb + (unsigned)t;
            u64 v0, v1, v2, v3;
            for (;;) {
                asm volatile("ld.relaxed.gpu.global.v2.u64 {%0,%1}, [%2];"
                             : "=l"(v0), "=l"(v1) : "l"(pp + 0) : "memory");
                asm volatile("ld.relaxed.gpu.global.v2.u64 {%0,%1}, [%2];"
                             : "=l"(v2), "=l"(v3) : "l"(pp + 2) : "memory");
                if (((unsigned)(v0 >> 32) == target) &
                    ((unsigned)(v1 >> 32) == target) &
                    ((unsigned)(v2 >> 32) == target) &
                    ((unsigned)(v3 >> 32) == target)) break;   // usually 1st try
            }
            mysh[0] = __uint_as_float((unsigned)v0);
            mysh[1] = __uint_as_float((unsigned)v1);
            mysh[2] = __uint_as_float((unsigned)v2);
            mysh[3] = __uint_as_float((unsigned)v3);
        }
        __syncthreads();       // BAR B: sh ready

        // zx prefetch for t+1 (overlaps compute)
        float zx_next = (zlane && t + 1 < Tm)
            ? __ldg(&g_zx[(size_t)(t + 1) * 4096 + blk * Dm + dim]) : 0.0f;

        // ---- partial dot: 128 k via 64 packed FMAs, 4 accumulator chains ----
        u64 a0 = 0ull, a1 = 0ull, a2 = 0ull, a3 = 0ull;
        const float4* sh4 = (const float4*)sh[t & 1];
#pragma unroll
        for (int f = 0; f < 32; f += 2) {
            float4 h0 = sh4[f * 8 + ch];
            float4 h1 = sh4[(f + 1) * 8 + ch];
            a0 = ffma2(pack2(h0.x, h0.y), wreg[2 * f + 0], a0);
            a1 = ffma2(pack2(h0.z, h0.w), wreg[2 * f + 1], a1);
            a2 = ffma2(pack2(h1.x, h1.y), wreg[2 * f + 2], a2);
            a3 = ffma2(pack2(h1.z, h1.w), wreg[2 * f + 3], a3);
        }
        float s = hsum2(fadd2(fadd2(a0, a1), fadd2(a2, a3)));
        if (zlane) s += zx_cur;                     // fold zx before reduce
        s += __shfl_xor_sync(0xffffffffu, s, 1);
        s += __shfl_xor_sync(0xffffffffu, s, 2);
        s += __shfl_xor_sync(0xffffffffu, s, 4);
        // s = z_blk on every lane of its blk group

        float v8 = __shfl_xor_sync(0xffffffffu, s, 8);  // pair gate's z
        float f1 = 0.0f, f2 = 0.0f, gv = 0.0f;
        if (blk == 0)      { f1 = fast_tanh(s);  f2 = fast_tanh(v8); }
        else if (blk == 1) { f1 = fast_tanh(v8); f2 = fast_tanh(s);  }
        else if (blk == 2) { gv = fast_sigmoid(v8 - s * dt); }   // zb - za*dt
        else               { gv = fast_sigmoid(s - v8 * dt); }
        float g  = __shfl_xor_sync(0xffffffffu, gv, 16);  // lanes 0-15 get g
        float hn = g * f1 + (1.0f - g) * f2;              // valid on lanes 0-15

        // ---- publish + hierarchical arrival (lane0), no CTA-wide BAR ----
        if (lane == 0 && t + 1 < Tm) {
            u64 pk = ((u64)(tagb + (unsigned)(t + 1)) << 32)
                   | (u64)__float_as_uint(hn);
            asm volatile("st.relaxed.gpu.global.b64 [%0], %1;"
                         :: "l"(&g_ht[(t + 1) & 1][dim]), "l"(pk) : "memory");
            unsigned old;
            asm volatile("atom.relaxed.cta.shared.add.u32 %0, [%1], %2;"
                         : "=r"(old) : "r"(acnt_a), "r"(1u) : "memory");
            if (old == 8u * (unsigned)t + 7u)      // 8th warp of this step
                asm volatile("red.relaxed.gpu.global.add.u32 [%0], %1;"
                             :: "l"(cnt), "r"(1u) : "memory");
        }

        // stash h_t; flush 16 steps at once (lanes 0-15 hold valid hn)
        if (lane == (t & 15)) h_keep = hn;
        if ((t & 15) == 15 && lane < 16) {
            int tb = t & ~15;
            outseq[(size_t)(tb + lane) * Dm + dim] = h_keep;
        }
        zx_cur = zx_next;
    }
}

// ---------------- kernel 4: emit final h -------------------------------------
__global__ void copy_out_kernel(float* __restrict__ out) {
    out[threadIdx.x] = g_seq[0][(size_t)(Tm - 1) * Dm + threadIdx.x];
}

// ---------------- launch ------------------------------------------------------
extern "C" void kernel_launch(void* const* d_in, const int* in_sizes, int n_in,
                              void* d_out, int out_size) {
    const float* x    = (const float*)d_in[0];
    const float* rn   = (const float*)d_in[1];
    const float* dtp  = (const float*)d_in[2];
    const float* rw   = (const float*)d_in[3];
    const float* rb   = (const float*)d_in[4];
    const float* Wf1  = (const float*)d_in[5];
    const float* bf1  = (const float*)d_in[6];
    const float* Wf2  = (const float*)d_in[7];
    const float* bf2  = (const float*)d_in[8];
    const float* Wta  = (const float*)d_in[9];
    const float* bta  = (const float*)d_in[10];
    const float* Wtb  = (const float*)d_in[11];
    const float* btb  = (const float*)d_in[12];

    // launch slots: 1=bias, 2=wt, 3=gemm0, 4=scan0, 5=gemm1, 6=scan1 (ncu -s5)
    bias_kernel<<<(Tm * Dm) / 256, 256>>>(x, rn, rw, rb);
    wt_kernel<<<dim3(32, 32, 16), dim3(32, 8)>>>(Wf1, Wf2, Wta, Wtb);

    for (int l = 0; l < Lm; ++l) {
        dim3 grid(4 * Dm / 128, Tm / 128);
        gemm_zx<<<grid, 256>>>(Wf1, Wf2, Wta, Wtb, bf1, bf2, bta, btb, l);
        scan_kernel<<<128, 256>>>(dtp, l);
    }

    copy_out_kernel<<<1, Dm>>>((float*)d_out);
}